// round 6
// baseline (speedup 1.0000x reference)
#include <cuda_runtime.h>

#define NMAX 40000
#define EMAX 640000

// Scratch (device globals: allocation-free per harness rules)
__device__ int   g_deg[NMAX];
__device__ int   g_rowptr[NMAX + 1];
__device__ int   g_cursor[NMAX];
__device__ int   g_col[EMAX];
__device__ float g_dinv[NMAX];
__device__ int   g_bsum[64];
__device__ float g_buf0[(size_t)NMAX * 128];
__device__ float g_buf1[(size_t)NMAX * 128];
// Pre-split bf16 fragment-ordered weights:
// entry ((kt*BN)+c)*4+qid -> uint4 {bh0, bh1, bl0, bl1} (bf16x2 each)
//   bh0: W[k0+2q],W[k0+2q+1] hi;  bh1: W[k0+2q+8],W[k0+2q+9] hi;  bl*: lo parts
__device__ uint4 g_pb1[8 * 128 * 4];
__device__ uint4 g_pb2[8 * 128 * 4];
__device__ uint4 g_pb3[8 * 64 * 4];

// ---------------------------------------------------------------------------
// bf16 split helpers
// ---------------------------------------------------------------------------
__device__ __forceinline__ unsigned pack_bf16x2(float flo, float fhi) {
    unsigned r;  // low half <- flo, high half <- fhi
    asm("cvt.rn.bf16x2.f32 %0, %1, %2;" : "=r"(r) : "f"(fhi), "f"(flo));
    return r;
}
// split two floats (consecutive k) into bf16x2 hi + bf16x2 lo
__device__ __forceinline__ void split2(float f0, float f1, unsigned& hi, unsigned& lo) {
    hi = pack_bf16x2(f0, f1);
    float h0 = __uint_as_float(hi << 16);
    float h1 = __uint_as_float(hi & 0xffff0000u);
    lo = pack_bf16x2(f0 - h0, f1 - h1);
}

// ---------------------------------------------------------------------------
// 0) fused prep: zero g_deg + pack all three weight matrices
// ---------------------------------------------------------------------------
__device__ __forceinline__ void pack_one(const float* __restrict__ W,
                                         uint4* __restrict__ PB, int BN, int j) {
    int qid = j & 3;
    int c   = (j >> 2) % BN;
    int kt  = (j >> 2) / BN;
    int k0  = kt * 16;
    float f0 = W[(k0 + 2 * qid)     * BN + c];
    float f1 = W[(k0 + 2 * qid + 1) * BN + c];
    float f2 = W[(k0 + 2 * qid + 8) * BN + c];
    float f3 = W[(k0 + 2 * qid + 9) * BN + c];
    uint4 v;
    split2(f0, f1, v.x, v.z);
    split2(f2, f3, v.y, v.w);
    PB[j] = v;
}

__global__ void prep_kernel(const float* __restrict__ W1,
                            const float* __restrict__ W2,
                            const float* __restrict__ W3, int N) {
    int i = blockIdx.x * blockDim.x + threadIdx.x;
    if (i < N) { g_deg[i] = 0; return; }
    i -= N;
    if (i < 8 * 128 * 4) { pack_one(W1, g_pb1, 128, i); return; }
    i -= 8 * 128 * 4;
    if (i < 8 * 128 * 4) { pack_one(W2, g_pb2, 128, i); return; }
    i -= 8 * 128 * 4;
    if (i < 8 * 64 * 4)  { pack_one(W3, g_pb3, 64, i); }
}

// ---------------------------------------------------------------------------
// 1) degree count (edges by dst)
// ---------------------------------------------------------------------------
__global__ void deg_kernel(const int* __restrict__ dst, int E, int N) {
    int i = blockIdx.x * blockDim.x + threadIdx.x;
    if (i < E) {
        int d = dst[i];
        d = max(0, min(d, N - 1));
        atomicAdd(&g_deg[d], 1);
    }
}

// ---------------------------------------------------------------------------
// 2) hierarchical exclusive scan -> rowptr/cursor + dinv
// ---------------------------------------------------------------------------
__global__ void scan1_kernel(int N) {
    __shared__ int sh[256];
    int t = threadIdx.x;
    int base = blockIdx.x * 1024 + t * 4;
    int s = 0;
    #pragma unroll
    for (int i = 0; i < 4; i++) if (base + i < N) s += g_deg[base + i];
    sh[t] = s;
    __syncthreads();
    #pragma unroll
    for (int off = 128; off > 0; off >>= 1) {
        if (t < off) sh[t] += sh[t + off];
        __syncthreads();
    }
    if (t == 0) g_bsum[blockIdx.x] = sh[0];
}

__global__ void scan2_kernel(int nb, int N) {
    if (threadIdx.x == 0) {
        int run = 0;
        for (int i = 0; i < nb; i++) { int v = g_bsum[i]; g_bsum[i] = run; run += v; }
        g_rowptr[N] = run;
    }
}

__global__ void scan3_kernel(int N) {
    __shared__ int sh[256];
    int t = threadIdx.x;
    int base = blockIdx.x * 1024 + t * 4;
    int v[4];
    int s = 0;
    #pragma unroll
    for (int i = 0; i < 4; i++) {
        v[i] = (base + i < N) ? g_deg[base + i] : 0;
        s += v[i];
    }
    sh[t] = s;
    __syncthreads();
    #pragma unroll
    for (int off = 1; off < 256; off <<= 1) {
        int x = (t >= off) ? sh[t - off] : 0;
        __syncthreads();
        sh[t] += x;
        __syncthreads();
    }
    int run = g_bsum[blockIdx.x] + sh[t] - s;
    #pragma unroll
    for (int i = 0; i < 4; i++) {
        int idx = base + i;
        if (idx < N) {
            g_rowptr[idx] = run;
            g_cursor[idx] = run;
            g_dinv[idx]   = rsqrtf((float)v[i] + 1.0f);
            run += v[i];
        }
    }
}

// ---------------------------------------------------------------------------
// 3) CSR fill
// ---------------------------------------------------------------------------
__global__ void fill_kernel(const int* __restrict__ src,
                            const int* __restrict__ dst, int E, int N) {
    int i = blockIdx.x * blockDim.x + threadIdx.x;
    if (i < E) {
        int d = max(0, min(dst[i], N - 1));
        int s = max(0, min(src[i], N - 1));
        int pos = atomicAdd(&g_cursor[d], 1);
        g_col[pos] = s;
    }
}

// ---------------------------------------------------------------------------
// 4) Tensor-core GEMM, split-bf16 3-product (ah*bh + ah*bl + al*bh), k16
// ---------------------------------------------------------------------------
__device__ __forceinline__ void mma_bf16(float* c, const unsigned* a, const unsigned* b) {
    asm volatile(
        "mma.sync.aligned.m16n8k16.row.col.f32.bf16.bf16.f32 "
        "{%0,%1,%2,%3}, {%4,%5,%6,%7}, {%8,%9}, {%0,%1,%2,%3};\n"
        : "+f"(c[0]), "+f"(c[1]), "+f"(c[2]), "+f"(c[3])
        : "r"(a[0]), "r"(a[1]), "r"(a[2]), "r"(a[3]), "r"(b[0]), "r"(b[1]));
}

template <int BN>
__global__ void __launch_bounds__(256, 1)
bf16_gemm_kernel(const float* __restrict__ A,
                 const uint4* __restrict__ PB,
                 float* __restrict__ C, int M) {
    constexpr int NT = BN / 16;           // n8-tiles per warp (covers BN/2 cols)
    int tid = threadIdx.x;
    int wid = tid >> 5, lane = tid & 31;
    int warp_m = wid >> 1, warp_n = wid & 1;
    int grp = lane >> 2, qid = lane & 3;
    int m0 = blockIdx.x * 128 + warp_m * 32;
    int col0 = warp_n * (BN / 2);

    float acc[2][NT][4];
    #pragma unroll
    for (int mt = 0; mt < 2; mt++)
        #pragma unroll
        for (int nt = 0; nt < NT; nt++)
            #pragma unroll
            for (int j = 0; j < 4; j++) acc[mt][nt][j] = 0.f;

    #pragma unroll
    for (int kt = 0; kt < 8; kt++) {
        int k0 = kt * 16;
        unsigned ahi[2][4], alo[2][4];
        #pragma unroll
        for (int mt = 0; mt < 2; mt++) {
            int r0 = m0 + mt * 16 + grp;
            int r1 = r0 + 8;
            int rc0 = min(r0, M - 1), rc1 = min(r1, M - 1);
            float2 p0 = *(const float2*)(A + (size_t)rc0 * 128 + k0 + 2 * qid);
            float2 p1 = *(const float2*)(A + (size_t)rc1 * 128 + k0 + 2 * qid);
            float2 p2 = *(const float2*)(A + (size_t)rc0 * 128 + k0 + 2 * qid + 8);
            float2 p3 = *(const float2*)(A + (size_t)rc1 * 128 + k0 + 2 * qid + 8);
            split2(p0.x, p0.y, ahi[mt][0], alo[mt][0]);
            split2(p1.x, p1.y, ahi[mt][1], alo[mt][1]);
            split2(p2.x, p2.y, ahi[mt][2], alo[mt][2]);
            split2(p3.x, p3.y, ahi[mt][3], alo[mt][3]);
        }
        #pragma unroll
        for (int nt = 0; nt < NT; nt++) {
            int c = col0 + nt * 8 + grp;
            uint4 pb = PB[((kt * BN) + c) * 4 + qid];
            unsigned bh[2] = { pb.x, pb.y };
            unsigned bl[2] = { pb.z, pb.w };
            #pragma unroll
            for (int mt = 0; mt < 2; mt++) {
                mma_bf16(acc[mt][nt], ahi[mt], bh);
                mma_bf16(acc[mt][nt], ahi[mt], bl);
                mma_bf16(acc[mt][nt], alo[mt], bh);
            }
        }
    }
    #pragma unroll
    for (int mt = 0; mt < 2; mt++) {
        int r0 = m0 + mt * 16 + grp;
        int r1 = r0 + 8;
        #pragma unroll
        for (int nt = 0; nt < NT; nt++) {
            int c = col0 + nt * 8 + qid * 2;
            if (r0 < M) {
                C[(size_t)r0 * BN + c]     = acc[mt][nt][0];
                C[(size_t)r0 * BN + c + 1] = acc[mt][nt][1];
            }
            if (r1 < M) {
                C[(size_t)r1 * BN + c]     = acc[mt][nt][2];
                C[(size_t)r1 * BN + c + 1] = acc[mt][nt][3];
            }
        }
    }
}

// ---------------------------------------------------------------------------
// 5) Aggregation D=128: warp per node, CSR gather, + self, + bias, ReLU
// ---------------------------------------------------------------------------
template <bool RELU>
__global__ void agg128_kernel(const float* __restrict__ hin,
                              float* __restrict__ hout,
                              const float* __restrict__ bias, int N) {
    int warp = (blockIdx.x * blockDim.x + threadIdx.x) >> 5;
    int lane = threadIdx.x & 31;
    if (warp >= N) return;

    float dn = g_dinv[warp];
    float acc[4];
    {
        float ws = dn * dn;
        float4 v = *(const float4*)(hin + (size_t)warp * 128 + lane * 4);
        acc[0] = ws * v.x; acc[1] = ws * v.y; acc[2] = ws * v.z; acc[3] = ws * v.w;
    }
    int e = g_rowptr[warp];
    const int e1 = g_rowptr[warp + 1];
    for (; e + 4 <= e1; e += 4) {
        int s0 = g_col[e], s1 = g_col[e + 1], s2 = g_col[e + 2], s3 = g_col[e + 3];
        float w0 = g_dinv[s0] * dn, w1 = g_dinv[s1] * dn;
        float w2 = g_dinv[s2] * dn, w3 = g_dinv[s3] * dn;
        float4 v0 = *(const float4*)(hin + (size_t)s0 * 128 + lane * 4);
        float4 v1 = *(const float4*)(hin + (size_t)s1 * 128 + lane * 4);
        float4 v2 = *(const float4*)(hin + (size_t)s2 * 128 + lane * 4);
        float4 v3 = *(const float4*)(hin + (size_t)s3 * 128 + lane * 4);
        acc[0] += w0 * v0.x + w1 * v1.x + w2 * v2.x + w3 * v3.x;
        acc[1] += w0 * v0.y + w1 * v1.y + w2 * v2.y + w3 * v3.y;
        acc[2] += w0 * v0.z + w1 * v1.z + w2 * v2.z + w3 * v3.z;
        acc[3] += w0 * v0.w + w1 * v1.w + w2 * v2.w + w3 * v3.w;
    }
    for (; e < e1; e++) {
        int s = g_col[e];
        float w = g_dinv[s] * dn;
        float4 v = *(const float4*)(hin + (size_t)s * 128 + lane * 4);
        acc[0] += w * v.x; acc[1] += w * v.y; acc[2] += w * v.z; acc[3] += w * v.w;
    }
    float4 b = *(const float4*)(bias + lane * 4);
    float4 o = make_float4(acc[0] + b.x, acc[1] + b.y, acc[2] + b.z, acc[3] + b.w);
    if (RELU) {
        o.x = fmaxf(o.x, 0.f); o.y = fmaxf(o.y, 0.f);
        o.z = fmaxf(o.z, 0.f); o.w = fmaxf(o.w, 0.f);
    }
    *(float4*)(hout + (size_t)warp * 128 + lane * 4) = o;
}

// ---------------------------------------------------------------------------
// 5b) Aggregation D=64 with fused output head
// ---------------------------------------------------------------------------
__global__ void agg64_out_kernel(const float* __restrict__ hin,
                                 float* __restrict__ hout,
                                 const float* __restrict__ bias,
                                 const float* __restrict__ Wout,
                                 const float* __restrict__ bout,
                                 float* __restrict__ out, int N) {
    int warp = (blockIdx.x * blockDim.x + threadIdx.x) >> 5;
    int lane = threadIdx.x & 31;
    if (warp >= N) return;

    float dn = g_dinv[warp];
    float a0, a1;
    {
        float ws = dn * dn;
        float2 v = *(const float2*)(hin + (size_t)warp * 64 + lane * 2);
        a0 = ws * v.x; a1 = ws * v.y;
    }
    int e = g_rowptr[warp];
    const int e1 = g_rowptr[warp + 1];
    for (; e + 4 <= e1; e += 4) {
        int s0 = g_col[e], s1 = g_col[e + 1], s2 = g_col[e + 2], s3 = g_col[e + 3];
        float w0 = g_dinv[s0] * dn, w1 = g_dinv[s1] * dn;
        float w2 = g_dinv[s2] * dn, w3 = g_dinv[s3] * dn;
        float2 v0 = *(const float2*)(hin + (size_t)s0 * 64 + lane * 2);
        float2 v1 = *(const float2*)(hin + (size_t)s1 * 64 + lane * 2);
        float2 v2 = *(const float2*)(hin + (size_t)s2 * 64 + lane * 2);
        float2 v3 = *(const float2*)(hin + (size_t)s3 * 64 + lane * 2);
        a0 += w0 * v0.x + w1 * v1.x + w2 * v2.x + w3 * v3.x;
        a1 += w0 * v0.y + w1 * v1.y + w2 * v2.y + w3 * v3.y;
    }
    for (; e < e1; e++) {
        int s = g_col[e];
        float w = g_dinv[s] * dn;
        float2 v = *(const float2*)(hin + (size_t)s * 64 + lane * 2);
        a0 += w * v.x; a1 += w * v.y;
    }
    float2 b = *(const float2*)(bias + lane * 2);
    float2 o = make_float2(a0 + b.x, a1 + b.y);
    *(float2*)(hout + (size_t)warp * 64 + lane * 2) = o;

    // fused head: out[warp][j] = sum_c h[c]*Wout[c][j] + bout[j]
    int c0 = lane * 2;
    float p0 = o.x * __ldg(&Wout[c0 * 2])     + o.y * __ldg(&Wout[(c0 + 1) * 2]);
    float p1 = o.x * __ldg(&Wout[c0 * 2 + 1]) + o.y * __ldg(&Wout[(c0 + 1) * 2 + 1]);
    #pragma unroll
    for (int off = 16; off > 0; off >>= 1) {
        p0 += __shfl_xor_sync(0xffffffffu, p0, off);
        p1 += __shfl_xor_sync(0xffffffffu, p1, off);
    }
    if (lane == 0) {
        out[(size_t)warp * 2 + 0] = p0 + __ldg(&bout[0]);
        out[(size_t)warp * 2 + 1] = p1 + __ldg(&bout[1]);
    }
}

// ---------------------------------------------------------------------------
extern "C" void kernel_launch(void* const* d_in, const int* in_sizes, int n_in,
                              void* d_out, int out_size) {
    (void)n_in; (void)out_size;
    const float* x    = (const float*)d_in[0];
    const int*   ei   = (const int*)d_in[1];   // int32 (JAX default x64 off)
    const float* W1   = (const float*)d_in[2];
    const float* b1   = (const float*)d_in[3];
    const float* W2   = (const float*)d_in[4];
    const float* b2   = (const float*)d_in[5];
    const float* W3   = (const float*)d_in[6];
    const float* b3   = (const float*)d_in[7];
    const float* Wout = (const float*)d_in[8];
    const float* bout = (const float*)d_in[9];

    int N = in_sizes[0] / 128;
    int E = in_sizes[1] / 2;

    float* out  = (float*)d_out;
    float* hout = out + (size_t)N * 2;   // tuple layout: out[N,2] then h[N,64]

    float* buf0; cudaGetSymbolAddress((void**)&buf0, g_buf0);
    float* buf1; cudaGetSymbolAddress((void**)&buf1, g_buf1);
    uint4* pb1; cudaGetSymbolAddress((void**)&pb1, g_pb1);
    uint4* pb2; cudaGetSymbolAddress((void**)&pb2, g_pb2);
    uint4* pb3; cudaGetSymbolAddress((void**)&pb3, g_pb3);

    const int* src = ei;
    const int* dst = ei + E;

    // fused prep: zero deg + pack three weight matrices
    int prep_total = N + 8 * 128 * 4 + 8 * 128 * 4 + 8 * 64 * 4;
    prep_kernel<<<(prep_total + 255) / 256, 256>>>(W1, W2, W3, N);

    // CSR build
    int nb = (N + 1023) / 1024;
    deg_kernel<<<(E + 255) / 256, 256>>>(dst, E, N);
    scan1_kernel<<<nb, 256>>>(N);
    scan2_kernel<<<1, 32>>>(nb, N);
    scan3_kernel<<<nb, 256>>>(N);
    fill_kernel<<<(E + 255) / 256, 256>>>(src, dst, E, N);

    int gM = (N + 127) / 128;
    int gW = (N * 32 + 255) / 256;

    // Layer 1
    bf16_gemm_kernel<128><<<gM, 256>>>(x, pb1, buf0, N);
    agg128_kernel<true><<<gW, 256>>>(buf0, buf1, b1, N);
    // Layer 2
    bf16_gemm_kernel<128><<<gM, 256>>>(buf1, pb2, buf0, N);
    agg128_kernel<true><<<gW, 256>>>(buf0, buf1, b2, N);
    // Layer 3 + fused output head
    bf16_gemm_kernel<64><<<gM, 256>>>(buf1, pb3, buf0, N);
    agg64_out_kernel<<<gW, 256>>>(buf0, hout, b3, Wout, bout, out, N);
}